// round 3
// baseline (speedup 1.0000x reference)
#include <cuda_runtime.h>

// ============================================================================
// STGCNEncoder — only row 0 of the GCN output feeds the GRU. Compute exactly
// that: one streaming pass over dst builds a full degree histogram (spread
// atomics into an L2-resident 400KB table) AND collects the ~32 edges into
// node 0. Then tiny fused GEMVs for encoder/GCN-row0/GRU.
// ============================================================================

#define CAP 2048          // capacity for dst==0 edge list (expected ~32)
#define NMAX 131072       // degree table capacity (N = 100000)

__device__ int   g_is64;          // 1 if edge_index is int64, 0 if int32
__device__ int   g_cnt;           // number of dst==0 edges collected
__device__ int   g_srcs[CAP];     // src node of each dst==0 edge
__device__ int   g_deg[NMAX];     // edge in-degree histogram (self-loop NOT included)
__device__ float g_g0[128];       // relu(agg[0] + b_gcn)
__device__ float g_gi[768];
__device__ float g_gh[768];

// ---------------------------------------------------------------------------
// Zero the degree table + scalars. Grid-strided.
__global__ void k_reset(int n) {
    long gid = (long)blockIdx.x * blockDim.x + threadIdx.x;
    if (gid == 0) { g_cnt = 0; g_is64 = 1; }
    long stride = (long)gridDim.x * blockDim.x;
    for (long i = gid; i < n; i += stride) g_deg[i] = 0;
}

// Detect dtype: if data is int64 (values in [0,1e5)), every odd 32-bit word
// is 0. If int32, odd words are random node ids — some nonzero w.p. ~1-1e-2500.
__global__ void k_detect(const int* __restrict__ w, int E) {
    int i = threadIdx.x;
    int bad = 0;
    if (w[2 * i + 1] != 0) bad = 1;
    if (w[2 * (i + 256) + 1] != 0) bad = 1;
    if (bad) atomicAnd(&g_is64, 0);
}

// THE streaming pass: histogram every dst (spread atomics, L2-resident table)
// and collect src of dst==0 edges. Vectorized 16B loads.
__global__ void k_main(const int* __restrict__ w, int E) {
    long gid = (long)blockIdx.x * blockDim.x + threadIdx.x;
    long stride = (long)gridDim.x * blockDim.x;
    if (g_is64) {
        const long long* src = (const long long*)w;
        const long long* dst = src + E;
        int n2 = E >> 1;
        const longlong2* dst2 = (const longlong2*)dst;
        for (long i = gid; i < n2; i += stride) {
            longlong2 v = dst2[i];
            int d0 = (int)v.x, d1 = (int)v.y;
            atomicAdd(&g_deg[d0], 1);
            atomicAdd(&g_deg[d1], 1);
            if (d0 == 0) {
                int p = atomicAdd(&g_cnt, 1);
                if (p < CAP) g_srcs[p] = (int)src[2 * i];
            }
            if (d1 == 0) {
                int p = atomicAdd(&g_cnt, 1);
                if (p < CAP) g_srcs[p] = (int)src[2 * i + 1];
            }
        }
        // tail (E odd)
        if (gid == 0 && (E & 1)) {
            int d = (int)dst[E - 1];
            atomicAdd(&g_deg[d], 1);
            if (d == 0) {
                int p = atomicAdd(&g_cnt, 1);
                if (p < CAP) g_srcs[p] = (int)src[E - 1];
            }
        }
    } else {
        const int* src = w;
        const int* dst = w + E;
        int n4 = E >> 2;
        const int4* dst4 = (const int4*)dst;
        for (long i = gid; i < n4; i += stride) {
            int4 v = dst4[i];
            atomicAdd(&g_deg[v.x], 1);
            atomicAdd(&g_deg[v.y], 1);
            atomicAdd(&g_deg[v.z], 1);
            atomicAdd(&g_deg[v.w], 1);
            int d[4] = {v.x, v.y, v.z, v.w};
            #pragma unroll
            for (int k = 0; k < 4; k++) {
                if (d[k] == 0) {
                    int p = atomicAdd(&g_cnt, 1);
                    if (p < CAP) g_srcs[p] = src[4 * i + k];
                }
            }
        }
        if (gid < (E & 3)) {
            long i = (long)(E & ~3) + gid;
            int dd = dst[i];
            atomicAdd(&g_deg[dd], 1);
            if (dd == 0) {
                int p = atomicAdd(&g_cnt, 1);
                if (p < CAP) g_srcs[p] = src[i];
            }
        }
    }
}

// Encoder + weighted sum + GCN GEMV for row 0. Single block, 256 threads.
// xsum = sum_i w_i * relu(W_enc @ f[s_i] + b_enc),  w_i = rsqrt(deg_i)*rsqrt(deg_0)
// g0 = relu(W_gcn @ xsum + b_gcn)
__global__ void k_gcn(const float* __restrict__ nf,
                      const float* __restrict__ W_enc,
                      const float* __restrict__ b_enc,
                      const float* __restrict__ W_gcn,
                      const float* __restrict__ b_gcn) {
    __shared__ float sWe[128 * 65];   // W_enc padded (stride 65 -> conflict-free)
    __shared__ float sPart[8][128];   // per-warp partial xsum
    __shared__ float sF[8][64];       // per-warp node feature buffer
    __shared__ float sXsum[128];
    __shared__ float sBenc[128];

    int t = threadIdx.x, lane = t & 31, w = t >> 5;

    for (int i = t; i < 128 * 64; i += 256) {
        int j = i >> 6, k = i & 63;
        sWe[j * 65 + k] = W_enc[i];
    }
    if (t < 128) sBenc[t] = b_enc[t];
    for (int i = t; i < 8 * 128; i += 256) ((float*)sPart)[i] = 0.0f;
    __syncthreads();

    int cnt = g_cnt; if (cnt > CAP) cnt = CAP;
    int M = cnt + 1;                               // + node 0 self-loop term
    float dinv0 = rsqrtf((float)g_deg[0] + 1.0f);  // +1 self loop

    for (int i = w; i < M; i += 8) {
        int s = (i < cnt) ? g_srcs[i] : 0;
        float wt = rsqrtf((float)g_deg[s] + 1.0f) * dinv0;
        sF[w][lane]      = nf[(long)s * 64 + lane];
        sF[w][lane + 32] = nf[(long)s * 64 + 32 + lane];
        __syncwarp();
        #pragma unroll
        for (int jj = 0; jj < 4; jj++) {
            int j = jj * 32 + lane;
            float acc = sBenc[j];
            const float* wr = &sWe[j * 65];
            #pragma unroll
            for (int k = 0; k < 64; k++) acc += wr[k] * sF[w][k];
            sPart[w][j] += wt * fmaxf(acc, 0.0f);
        }
        __syncwarp();
    }
    __syncthreads();

    if (t < 128) {
        float xs = 0.0f;
        #pragma unroll
        for (int ww = 0; ww < 8; ww++) xs += sPart[ww][t];
        sXsum[t] = xs;
    }
    __syncthreads();

    // GCN GEMV: warp per output row, coalesced W_gcn reads + shuffle reduce
    for (int j = w; j < 128; j += 8) {
        float a = 0.0f;
        #pragma unroll
        for (int kk = 0; kk < 4; kk++) {
            int k = kk * 32 + lane;
            a += W_gcn[j * 128 + k] * sXsum[k];
        }
        #pragma unroll
        for (int off = 16; off; off >>= 1) a += __shfl_down_sync(0xffffffffu, a, off);
        if (lane == 0) g_g0[j] = fmaxf(a + b_gcn[j], 0.0f);
    }
}

// GRU GEMVs: 1536 warp-tasks (768 rows of W_ih@g0, 768 rows of W_hh@h).
__global__ void k_gru(const float* __restrict__ W_ih,
                      const float* __restrict__ W_hh,
                      const float* __restrict__ b_ih,
                      const float* __restrict__ b_hh,
                      const float* __restrict__ h) {
    __shared__ float sg0[128];
    int t = threadIdx.x, lane = t & 31, w = t >> 5;
    if (t < 128) sg0[t] = g_g0[t];
    __syncthreads();

    int task = blockIdx.x * 8 + w;
    if (task < 768) {
        const float* wr = W_ih + task * 128;
        float a = 0.0f;
        #pragma unroll
        for (int kk = 0; kk < 4; kk++) {
            int k = kk * 32 + lane;
            a += wr[k] * sg0[k];
        }
        #pragma unroll
        for (int off = 16; off; off >>= 1) a += __shfl_down_sync(0xffffffffu, a, off);
        if (lane == 0) g_gi[task] = a + b_ih[task];
    } else {
        int r = task - 768;
        const float* wr = W_hh + r * 256;
        float a = 0.0f;
        #pragma unroll
        for (int kk = 0; kk < 8; kk++) {
            int k = kk * 32 + lane;
            a += wr[k] * h[k];
        }
        #pragma unroll
        for (int off = 16; off; off >>= 1) a += __shfl_down_sync(0xffffffffu, a, off);
        if (lane == 0) g_gh[r] = a + b_hh[r];
    }
}

// Final gates.
__global__ void k_out(const float* __restrict__ h, float* __restrict__ out) {
    int c = threadIdx.x;
    float r  = 1.0f / (1.0f + expf(-(g_gi[c]       + g_gh[c])));
    float z  = 1.0f / (1.0f + expf(-(g_gi[256 + c] + g_gh[256 + c])));
    float nn = tanhf(g_gi[512 + c] + r * g_gh[512 + c]);
    out[c] = (1.0f - z) * nn + z * h[c];
}

// ---------------------------------------------------------------------------
extern "C" void kernel_launch(void* const* d_in, const int* in_sizes, int n_in,
                              void* d_out, int out_size) {
    const float* nf    = (const float*)d_in[0];
    // d_in[1] = edge_attr (unused by reference)
    const float* h     = (const float*)d_in[2];
    const float* W_enc = (const float*)d_in[3];
    const float* b_enc = (const float*)d_in[4];
    const float* W_gcn = (const float*)d_in[5];
    const float* b_gcn = (const float*)d_in[6];
    const float* W_ih  = (const float*)d_in[7];
    const float* W_hh  = (const float*)d_in[8];
    const float* b_ih  = (const float*)d_in[9];
    const float* b_hh  = (const float*)d_in[10];
    const int*   ei    = (const int*)d_in[11];  // int32 view; dtype detected on device
    int E = in_sizes[11] / 2;
    int n = in_sizes[0] / 64;
    if (n > NMAX) n = NMAX;
    float* out = (float*)d_out;

    int nb = (E / 2 + 255) / 256;
    if (nb > 2048) nb = 2048;

    k_reset  <<<256, 256>>>(n);
    k_detect <<<1, 256>>>(ei, E);
    k_main   <<<nb, 256>>>(ei, E);
    k_gcn    <<<1, 256>>>(nf, W_enc, b_enc, W_gcn, b_gcn);
    k_gru    <<<192, 256>>>(W_ih, W_hh, b_ih, b_hh, h);
    k_out    <<<1, 256>>>(h, out);
}

// round 4
// speedup vs baseline: 1.1474x; 1.1474x over previous
#include <cuda_runtime.h>

// ============================================================================
// STGCNEncoder — only row 0 of the GCN output feeds the GRU. One streaming
// pass over dst builds a degree histogram (spread atomics, L2-resident table)
// and collects the ~32 edges into node 0. Encoder GEMVs for those nodes run
// block-parallel; then tiny GCN-row0 + GRU GEMVs.
// ============================================================================

#define CAP 2048          // capacity for dst==0 edge list (expected ~32)
#define NMAX 131072       // degree table capacity (N = 100000)

__device__ int   g_is64;              // 1 if edge_index is int64, 0 if int32
__device__ int   g_cnt;               // number of dst==0 edges collected
__device__ int   g_srcs[CAP];         // src node of each dst==0 edge
__device__ int   g_deg[NMAX];         // edge in-degree histogram (no self-loop)
__device__ float g_ybuf[CAP + 1][128]; // per-term weighted encoder outputs
__device__ float g_g0[128];           // relu(agg[0] + b_gcn)
__device__ float g_gi[768];
__device__ float g_gh[768];

// ---------------------------------------------------------------------------
__global__ void k_reset(int n) {
    long gid = (long)blockIdx.x * blockDim.x + threadIdx.x;
    if (gid == 0) { g_cnt = 0; g_is64 = 1; }
    long stride = (long)gridDim.x * blockDim.x;
    for (long i = gid; i < n; i += stride) g_deg[i] = 0;
}

// Detect dtype: if data is int64 (values in [0,1e5)), every odd 32-bit word
// is 0. If int32, odd words are random node ids — nonzero w.p. ~1-1e-2500.
__global__ void k_detect(const int* __restrict__ w, int E) {
    int i = threadIdx.x;
    int bad = 0;
    if (w[2 * i + 1] != 0) bad = 1;
    if (w[2 * (i + 256) + 1] != 0) bad = 1;
    if (bad) atomicAnd(&g_is64, 0);
}

// Streaming pass: histogram every dst + collect src of dst==0 edges.
__global__ void k_main(const int* __restrict__ w, int E) {
    long gid = (long)blockIdx.x * blockDim.x + threadIdx.x;
    long stride = (long)gridDim.x * blockDim.x;
    if (g_is64) {
        const long long* src = (const long long*)w;
        const long long* dst = src + E;
        int n2 = E >> 1;
        const longlong2* dst2 = (const longlong2*)dst;
        for (long i = gid; i < n2; i += stride) {
            longlong2 v = dst2[i];
            int d0 = (int)v.x, d1 = (int)v.y;
            atomicAdd(&g_deg[d0], 1);
            atomicAdd(&g_deg[d1], 1);
            if (d0 == 0) {
                int p = atomicAdd(&g_cnt, 1);
                if (p < CAP) g_srcs[p] = (int)src[2 * i];
            }
            if (d1 == 0) {
                int p = atomicAdd(&g_cnt, 1);
                if (p < CAP) g_srcs[p] = (int)src[2 * i + 1];
            }
        }
        if (gid == 0 && (E & 1)) {
            int d = (int)dst[E - 1];
            atomicAdd(&g_deg[d], 1);
            if (d == 0) {
                int p = atomicAdd(&g_cnt, 1);
                if (p < CAP) g_srcs[p] = (int)src[E - 1];
            }
        }
    } else {
        const int* src = w;
        const int* dst = w + E;
        int n4 = E >> 2;
        const int4* dst4 = (const int4*)dst;
        for (long i = gid; i < n4; i += stride) {
            int4 v = dst4[i];
            atomicAdd(&g_deg[v.x], 1);
            atomicAdd(&g_deg[v.y], 1);
            atomicAdd(&g_deg[v.z], 1);
            atomicAdd(&g_deg[v.w], 1);
            int d[4] = {v.x, v.y, v.z, v.w};
            #pragma unroll
            for (int k = 0; k < 4; k++) {
                if (d[k] == 0) {
                    int p = atomicAdd(&g_cnt, 1);
                    if (p < CAP) g_srcs[p] = src[4 * i + k];
                }
            }
        }
        if (gid < (E & 3)) {
            long i = (long)(E & ~3) + gid;
            int dd = dst[i];
            atomicAdd(&g_deg[dd], 1);
            if (dd == 0) {
                int p = atomicAdd(&g_cnt, 1);
                if (p < CAP) g_srcs[p] = src[i];
            }
        }
    }
}

// Block-parallel encoder: term i -> y_i = wt_i * relu(W_enc @ f_{s_i} + b_enc).
// Warp-per-row GEMV straight from gmem (W_enc is L2-hot across blocks).
__global__ void k_enc(const float* __restrict__ nf,
                      const float* __restrict__ W_enc,
                      const float* __restrict__ b_enc) {
    __shared__ float sF[64];
    int t = threadIdx.x, lane = t & 31, w = t >> 5;

    int cnt = g_cnt; if (cnt > CAP) cnt = CAP;
    int M = cnt + 1;                               // + node-0 self-loop term
    float dinv0 = rsqrtf((float)g_deg[0] + 1.0f);  // +1 self loop

    for (int i = blockIdx.x; i < M; i += gridDim.x) {
        int s = (i < cnt) ? g_srcs[i] : 0;
        float wt = rsqrtf((float)g_deg[s] + 1.0f) * dinv0;
        if (t < 64) sF[t] = nf[(long)s * 64 + t];
        __syncthreads();
        float f0 = sF[lane], f1 = sF[32 + lane];
        #pragma unroll
        for (int jj = 0; jj < 16; jj++) {
            int j = jj * 8 + w;
            const float* wr = W_enc + j * 64;
            float a = wr[lane] * f0 + wr[32 + lane] * f1;
            #pragma unroll
            for (int off = 16; off; off >>= 1)
                a += __shfl_down_sync(0xffffffffu, a, off);
            if (lane == 0)
                g_ybuf[i][j] = wt * fmaxf(a + b_enc[j], 0.0f);
        }
        __syncthreads();
    }
}

// Sum encoder terms, then GCN GEMV for row 0: g0 = relu(W_gcn @ xsum + b_gcn).
__global__ void k_gcn2(const float* __restrict__ W_gcn,
                       const float* __restrict__ b_gcn) {
    __shared__ float sXsum[128];
    int t = threadIdx.x, lane = t & 31, w = t >> 5;

    int cnt = g_cnt; if (cnt > CAP) cnt = CAP;
    int M = cnt + 1;

    if (t < 128) {
        float xs = 0.0f;
        for (int i = 0; i < M; i++) xs += g_ybuf[i][t];
        sXsum[t] = xs;
    }
    __syncthreads();

    #pragma unroll
    for (int jj = 0; jj < 16; jj++) {
        int j = jj * 8 + w;
        float a = 0.0f;
        #pragma unroll
        for (int kk = 0; kk < 4; kk++) {
            int k = kk * 32 + lane;
            a += W_gcn[j * 128 + k] * sXsum[k];
        }
        #pragma unroll
        for (int off = 16; off; off >>= 1) a += __shfl_down_sync(0xffffffffu, a, off);
        if (lane == 0) g_g0[j] = fmaxf(a + b_gcn[j], 0.0f);
    }
}

// GRU GEMVs: 1536 warp-tasks (768 rows of W_ih@g0, 768 rows of W_hh@h).
__global__ void k_gru(const float* __restrict__ W_ih,
                      const float* __restrict__ W_hh,
                      const float* __restrict__ b_ih,
                      const float* __restrict__ b_hh,
                      const float* __restrict__ h) {
    __shared__ float sg0[128];
    int t = threadIdx.x, lane = t & 31, w = t >> 5;
    if (t < 128) sg0[t] = g_g0[t];
    __syncthreads();

    int task = blockIdx.x * 8 + w;
    if (task < 768) {
        const float* wr = W_ih + task * 128;
        float a = 0.0f;
        #pragma unroll
        for (int kk = 0; kk < 4; kk++) {
            int k = kk * 32 + lane;
            a += wr[k] * sg0[k];
        }
        #pragma unroll
        for (int off = 16; off; off >>= 1) a += __shfl_down_sync(0xffffffffu, a, off);
        if (lane == 0) g_gi[task] = a + b_ih[task];
    } else {
        int r = task - 768;
        const float* wr = W_hh + r * 256;
        float a = 0.0f;
        #pragma unroll
        for (int kk = 0; kk < 8; kk++) {
            int k = kk * 32 + lane;
            a += wr[k] * h[k];
        }
        #pragma unroll
        for (int off = 16; off; off >>= 1) a += __shfl_down_sync(0xffffffffu, a, off);
        if (lane == 0) g_gh[r] = a + b_hh[r];
    }
}

// Final gates.
__global__ void k_out(const float* __restrict__ h, float* __restrict__ out) {
    int c = threadIdx.x;
    float r  = 1.0f / (1.0f + expf(-(g_gi[c]       + g_gh[c])));
    float z  = 1.0f / (1.0f + expf(-(g_gi[256 + c] + g_gh[256 + c])));
    float nn = tanhf(g_gi[512 + c] + r * g_gh[512 + c]);
    out[c] = (1.0f - z) * nn + z * h[c];
}

// ---------------------------------------------------------------------------
extern "C" void kernel_launch(void* const* d_in, const int* in_sizes, int n_in,
                              void* d_out, int out_size) {
    const float* nf    = (const float*)d_in[0];
    // d_in[1] = edge_attr (unused by reference)
    const float* h     = (const float*)d_in[2];
    const float* W_enc = (const float*)d_in[3];
    const float* b_enc = (const float*)d_in[4];
    const float* W_gcn = (const float*)d_in[5];
    const float* b_gcn = (const float*)d_in[6];
    const float* W_ih  = (const float*)d_in[7];
    const float* W_hh  = (const float*)d_in[8];
    const float* b_ih  = (const float*)d_in[9];
    const float* b_hh  = (const float*)d_in[10];
    const int*   ei    = (const int*)d_in[11];  // int32 view; dtype detected on device
    int E = in_sizes[11] / 2;
    int n = in_sizes[0] / 64;
    if (n > NMAX) n = NMAX;
    float* out = (float*)d_out;

    int nb = (E / 2 + 255) / 256;
    if (nb > 2048) nb = 2048;

    k_reset  <<<256, 256>>>(n);
    k_detect <<<1, 256>>>(ei, E);
    k_main   <<<nb, 256>>>(ei, E);
    k_enc    <<<64, 256>>>(nf, W_enc, b_enc);
    k_gcn2   <<<1, 256>>>(W_gcn, b_gcn);
    k_gru    <<<192, 256>>>(W_ih, W_hh, b_ih, b_hh, h);
    k_out    <<<1, 256>>>(h, out);
}

// round 5
// speedup vs baseline: 1.4515x; 1.2650x over previous
#include <cuda_runtime.h>

// ============================================================================
// STGCNEncoder — fully fused single persistent kernel.
// Only row 0 of the GCN output feeds the GRU. Phases (grid-barrier separated):
//  0: init + dtype detect          4: encoder GEMVs (block per term)
//  1: stream dst, collect dst==0   5: xsum + GCN row0 (blk0) | weight prefetch
//  2: build ~34-node hash (blk0)   6: GRU GEMVs (warp per row)
//  3: L2-hot membership count      7: gates -> out (blk0)
// ============================================================================

#define G    148
#define B    512
#define CAP  2048
#define HSZ  4096
#define HMASK (HSZ - 1)

__device__ unsigned long long g_bar;   // monotonic grid-barrier counter
__device__ int   g_is64;
__device__ int   g_cnt;
__device__ int   g_srcs[CAP];
__device__ int   g_keys[HSZ];          // open-addressed set (node ids), -1 empty
__device__ int   g_hcnt[HSZ];          // per-slot dst-occurrence counts
__device__ float g_ybuf[CAP + 1][128];
__device__ float g_g0[128];
__device__ float g_gi[768];
__device__ float g_gh[768];

__device__ __forceinline__ void gbar() {
    __threadfence();
    __syncthreads();
    if (threadIdx.x == 0) {
        unsigned long long t = atomicAdd(&g_bar, 1ULL);
        unsigned long long target = t - (t % G) + G;
        volatile unsigned long long* p = &g_bar;
        while (*p < target) __nanosleep(32);
    }
    __syncthreads();
    __threadfence();
}

__device__ __forceinline__ unsigned hashi(int x) {
    return ((unsigned)x * 2654435761u) & HMASK;
}

__device__ __forceinline__ void insert_key(int key) {
    unsigned s = hashi(key);
    while (true) {
        int prev = atomicCAS(&g_keys[s], -1, key);
        if (prev == -1 || prev == key) return;
        s = (s + 1) & HMASK;
    }
}

__device__ __forceinline__ int lookup_cnt(int key) {
    unsigned s = hashi(key);
    while (true) {
        int k = g_keys[s];
        if (k == key) return g_hcnt[s];
        if (k == -1) return 0;
        s = (s + 1) & HMASK;
    }
}

__device__ __forceinline__ void count_d(int d, const int* sKeys, int* sCnt) {
    unsigned s = hashi(d);
    while (true) {
        int k = sKeys[s];
        if (k == -1) return;                       // common path: 1 LDS, miss
        if (k == d) { atomicAdd(&sCnt[s], 1); return; }
        s = (s + 1) & HMASK;
    }
}

__device__ __forceinline__ void hit0(const long long* src, long idx) {
    int p = atomicAdd(&g_cnt, 1);
    if (p < CAP) g_srcs[p] = (int)src[idx];
}
__device__ __forceinline__ void hit0i(const int* src, long idx) {
    int p = atomicAdd(&g_cnt, 1);
    if (p < CAP) g_srcs[p] = src[idx];
}

__global__ void __launch_bounds__(B, 1) k_fused(
    const float* __restrict__ nf, const float* __restrict__ h,
    const float* __restrict__ W_enc, const float* __restrict__ b_enc,
    const float* __restrict__ W_gcn, const float* __restrict__ b_gcn,
    const float* __restrict__ W_ih, const float* __restrict__ W_hh,
    const float* __restrict__ b_ih, const float* __restrict__ b_hh,
    const int* __restrict__ w, int E, float* __restrict__ out)
{
    __shared__ int   sKeys[HSZ];   // 16KB
    __shared__ int   sCnt[HSZ];    // 16KB
    __shared__ float sF[64];
    __shared__ float sX[128];

    const int t = threadIdx.x, lane = t & 31, wid = t >> 5;
    const int bid = blockIdx.x;
    const long gid = (long)bid * B + t;
    const long stride = (long)G * B;

    // ---- Phase 0: init + dtype detect (block 0 only) ----
    if (bid == 0) {
        if (t == 0) { g_cnt = 0; g_is64 = 1; }
        for (int i = t; i < HSZ; i += B) { g_keys[i] = -1; g_hcnt[i] = 0; }
        __syncthreads();
        // int64 data (ids < 1e5): every odd 32-bit word of src is 0.
        int bad = 0;
        long S = 2L * E;
        for (int i = t; i < 1024; i += B) {
            long idx = 2L * i + 1;
            if (idx < S && w[idx] != 0) bad = 1;
        }
        if (bad) atomicAnd(&g_is64, 0);
    }
    gbar();

    const int is64 = g_is64;

    // ---- Phase 1: stream dst, collect src of dst==0 edges ----
    if (is64) {
        const long long* src = (const long long*)w;
        const long long* dst = src + E;
        long n2 = (E & 1) ? 0 : (E >> 1);          // vec path only if aligned
        const longlong2* dst2 = (const longlong2*)dst;
        long i = gid;
        for (; i + 3 * stride < n2; i += 4 * stride) {
            longlong2 v0 = dst2[i];
            longlong2 v1 = dst2[i + stride];
            longlong2 v2 = dst2[i + 2 * stride];
            longlong2 v3 = dst2[i + 3 * stride];
            if (v0.x == 0) hit0(src, 2 * i);
            if (v0.y == 0) hit0(src, 2 * i + 1);
            if (v1.x == 0) hit0(src, 2 * (i + stride));
            if (v1.y == 0) hit0(src, 2 * (i + stride) + 1);
            if (v2.x == 0) hit0(src, 2 * (i + 2 * stride));
            if (v2.y == 0) hit0(src, 2 * (i + 2 * stride) + 1);
            if (v3.x == 0) hit0(src, 2 * (i + 3 * stride));
            if (v3.y == 0) hit0(src, 2 * (i + 3 * stride) + 1);
        }
        for (; i < n2; i += stride) {
            longlong2 v = dst2[i];
            if (v.x == 0) hit0(src, 2 * i);
            if (v.y == 0) hit0(src, 2 * i + 1);
        }
        for (long j = 2 * n2 + gid; j < E; j += stride)
            if (dst[j] == 0) hit0(src, j);
    } else {
        const int* src = w;
        const int* dst = w + E;
        long n4 = (E & 3) ? 0 : (E >> 2);
        const int4* dst4 = (const int4*)dst;
        long i = gid;
        for (; i + 3 * stride < n4; i += 4 * stride) {
            int4 v0 = dst4[i];
            int4 v1 = dst4[i + stride];
            int4 v2 = dst4[i + 2 * stride];
            int4 v3 = dst4[i + 3 * stride];
            long b0 = 4 * i, b1 = 4 * (i + stride), b2 = 4 * (i + 2 * stride), b3 = 4 * (i + 3 * stride);
            if (v0.x == 0) hit0i(src, b0);     if (v0.y == 0) hit0i(src, b0 + 1);
            if (v0.z == 0) hit0i(src, b0 + 2); if (v0.w == 0) hit0i(src, b0 + 3);
            if (v1.x == 0) hit0i(src, b1);     if (v1.y == 0) hit0i(src, b1 + 1);
            if (v1.z == 0) hit0i(src, b1 + 2); if (v1.w == 0) hit0i(src, b1 + 3);
            if (v2.x == 0) hit0i(src, b2);     if (v2.y == 0) hit0i(src, b2 + 1);
            if (v2.z == 0) hit0i(src, b2 + 2); if (v2.w == 0) hit0i(src, b2 + 3);
            if (v3.x == 0) hit0i(src, b3);     if (v3.y == 0) hit0i(src, b3 + 1);
            if (v3.z == 0) hit0i(src, b3 + 2); if (v3.w == 0) hit0i(src, b3 + 3);
        }
        for (; i < n4; i += stride) {
            int4 v = dst4[i];
            long b0 = 4 * i;
            if (v.x == 0) hit0i(src, b0);     if (v.y == 0) hit0i(src, b0 + 1);
            if (v.z == 0) hit0i(src, b0 + 2); if (v.w == 0) hit0i(src, b0 + 3);
        }
        for (long j = 4 * n4 + gid; j < E; j += stride)
            if (dst[j] == 0) hit0i(src, j);
    }
    gbar();

    int cnt = g_cnt; if (cnt > CAP) cnt = CAP;
    const int M = cnt + 1;                         // + node-0 self-loop term

    // ---- Phase 2: build key set (block 0) ----
    if (bid == 0) {
        for (int i = t; i < cnt; i += B) insert_key(g_srcs[i]);
        if (t == 0) insert_key(0);
    }
    gbar();

    // ---- Phase 3: L2-hot membership count pass ----
    for (int i = t; i < HSZ; i += B) { sKeys[i] = g_keys[i]; sCnt[i] = 0; }
    __syncthreads();
    if (is64) {
        const long long* dst = ((const long long*)w) + E;
        long n2 = (E & 1) ? 0 : (E >> 1);
        const longlong2* dst2 = (const longlong2*)dst;
        long i = gid;
        for (; i + 3 * stride < n2; i += 4 * stride) {
            longlong2 v0 = dst2[i];
            longlong2 v1 = dst2[i + stride];
            longlong2 v2 = dst2[i + 2 * stride];
            longlong2 v3 = dst2[i + 3 * stride];
            count_d((int)v0.x, sKeys, sCnt); count_d((int)v0.y, sKeys, sCnt);
            count_d((int)v1.x, sKeys, sCnt); count_d((int)v1.y, sKeys, sCnt);
            count_d((int)v2.x, sKeys, sCnt); count_d((int)v2.y, sKeys, sCnt);
            count_d((int)v3.x, sKeys, sCnt); count_d((int)v3.y, sKeys, sCnt);
        }
        for (; i < n2; i += stride) {
            longlong2 v = dst2[i];
            count_d((int)v.x, sKeys, sCnt); count_d((int)v.y, sKeys, sCnt);
        }
        for (long j = 2 * n2 + gid; j < E; j += stride)
            count_d((int)dst[j], sKeys, sCnt);
    } else {
        const int* dst = w + E;
        long n4 = (E & 3) ? 0 : (E >> 2);
        const int4* dst4 = (const int4*)dst;
        long i = gid;
        for (; i + 3 * stride < n4; i += 4 * stride) {
            int4 v0 = dst4[i];
            int4 v1 = dst4[i + stride];
            int4 v2 = dst4[i + 2 * stride];
            int4 v3 = dst4[i + 3 * stride];
            count_d(v0.x, sKeys, sCnt); count_d(v0.y, sKeys, sCnt);
            count_d(v0.z, sKeys, sCnt); count_d(v0.w, sKeys, sCnt);
            count_d(v1.x, sKeys, sCnt); count_d(v1.y, sKeys, sCnt);
            count_d(v1.z, sKeys, sCnt); count_d(v1.w, sKeys, sCnt);
            count_d(v2.x, sKeys, sCnt); count_d(v2.y, sKeys, sCnt);
            count_d(v2.z, sKeys, sCnt); count_d(v2.w, sKeys, sCnt);
            count_d(v3.x, sKeys, sCnt); count_d(v3.y, sKeys, sCnt);
            count_d(v3.z, sKeys, sCnt); count_d(v3.w, sKeys, sCnt);
        }
        for (; i < n4; i += stride) {
            int4 v = dst4[i];
            count_d(v.x, sKeys, sCnt); count_d(v.y, sKeys, sCnt);
            count_d(v.z, sKeys, sCnt); count_d(v.w, sKeys, sCnt);
        }
        for (long j = 4 * n4 + gid; j < E; j += stride)
            count_d(dst[j], sKeys, sCnt);
    }
    __syncthreads();
    for (int i = t; i < HSZ; i += B)
        if (sCnt[i]) atomicAdd(&g_hcnt[i], sCnt[i]);
    gbar();

    // ---- Phase 4: encoder terms: y_i = wt_i * relu(W_enc @ f_{s_i} + b_enc) ----
    for (int i = bid; i < M; i += G) {
        float dinv0 = rsqrtf((float)lookup_cnt(0) + 1.0f);   // +1 self loop
        int s = (i < cnt) ? g_srcs[i] : 0;
        float wt = rsqrtf((float)lookup_cnt(s) + 1.0f) * dinv0;
        if (t < 64) sF[t] = nf[(long)s * 64 + t];
        __syncthreads();
        float f0 = sF[lane], f1 = sF[lane + 32];
        #pragma unroll
        for (int jj = 0; jj < 8; jj++) {
            int j = wid * 8 + jj;
            const float* wr = W_enc + j * 64;
            float a = wr[lane] * f0 + wr[lane + 32] * f1;
            #pragma unroll
            for (int off = 16; off; off >>= 1)
                a += __shfl_down_sync(0xffffffffu, a, off);
            if (lane == 0) g_ybuf[i][j] = wt * fmaxf(a + b_enc[j], 0.0f);
        }
        __syncthreads();
    }
    gbar();

    // ---- Phase 5: xsum + GCN row0 (block 0); others prefetch GRU weights ----
    if (bid == 0) {
        if (t < 128) {
            float xs = 0.0f;
            for (int i = 0; i < M; i++) xs += g_ybuf[i][t];
            sX[t] = xs;
        }
        __syncthreads();
        #pragma unroll
        for (int jj = 0; jj < 8; jj++) {
            int j = wid * 8 + jj;
            float a = 0.0f;
            #pragma unroll
            for (int kk = 0; kk < 4; kk++)
                a += W_gcn[j * 128 + kk * 32 + lane] * sX[kk * 32 + lane];
            #pragma unroll
            for (int off = 16; off; off >>= 1)
                a += __shfl_down_sync(0xffffffffu, a, off);
            if (lane == 0) g_g0[j] = fmaxf(a + b_gcn[j], 0.0f);
        }
    } else {
        // warm L2 with GRU weights while block 0 computes g0
        float acc = 0.0f;
        const float4* p1 = (const float4*)W_ih;   // 768*128/4  = 24576
        const float4* p2 = (const float4*)W_hh;   // 768*256/4  = 49152
        long st2 = (long)(G - 1) * B;
        for (long i = (long)(bid - 1) * B + t; i < 24576; i += st2) {
            float4 v = p1[i]; acc += v.x + v.w;
        }
        for (long i = (long)(bid - 1) * B + t; i < 49152; i += st2) {
            float4 v = p2[i]; acc += v.x + v.w;
        }
        asm volatile("" :: "f"(acc));              // keep the loads
    }
    gbar();

    // ---- Phase 6: GRU GEMVs (warp per row; 1536 rows over 2368 warps) ----
    {
        int gw = bid * 16 + wid;
        if (gw < 768) {
            const float* wr = W_ih + gw * 128;
            float a = 0.0f;
            #pragma unroll
            for (int kk = 0; kk < 4; kk++)
                a += wr[kk * 32 + lane] * g_g0[kk * 32 + lane];
            #pragma unroll
            for (int off = 16; off; off >>= 1)
                a += __shfl_down_sync(0xffffffffu, a, off);
            if (lane == 0) g_gi[gw] = a + b_ih[gw];
        } else if (gw < 1536) {
            int r = gw - 768;
            const float* wr = W_hh + r * 256;
            float a = 0.0f;
            #pragma unroll
            for (int kk = 0; kk < 8; kk++)
                a += wr[kk * 32 + lane] * h[kk * 32 + lane];
            #pragma unroll
            for (int off = 16; off; off >>= 1)
                a += __shfl_down_sync(0xffffffffu, a, off);
            if (lane == 0) g_gh[r] = a + b_hh[r];
        }
    }
    gbar();

    // ---- Phase 7: gates -> out (block 0) ----
    if (bid == 0 && t < 256) {
        float r  = 1.0f / (1.0f + expf(-(g_gi[t]       + g_gh[t])));
        float z  = 1.0f / (1.0f + expf(-(g_gi[256 + t] + g_gh[256 + t])));
        float nn = tanhf(g_gi[512 + t] + r * g_gh[512 + t]);
        out[t] = (1.0f - z) * nn + z * h[t];
    }
}

// ---------------------------------------------------------------------------
extern "C" void kernel_launch(void* const* d_in, const int* in_sizes, int n_in,
                              void* d_out, int out_size) {
    const float* nf    = (const float*)d_in[0];
    // d_in[1] = edge_attr (unused by reference)
    const float* h     = (const float*)d_in[2];
    const float* W_enc = (const float*)d_in[3];
    const float* b_enc = (const float*)d_in[4];
    const float* W_gcn = (const float*)d_in[5];
    const float* b_gcn = (const float*)d_in[6];
    const float* W_ih  = (const float*)d_in[7];
    const float* W_hh  = (const float*)d_in[8];
    const float* b_ih  = (const float*)d_in[9];
    const float* b_hh  = (const float*)d_in[10];
    const int*   ei    = (const int*)d_in[11];  // int32 view; dtype detected on device
    int E = in_sizes[11] / 2;
    float* out = (float*)d_out;

    k_fused<<<G, B>>>(nf, h, W_enc, b_enc, W_gcn, b_gcn,
                      W_ih, W_hh, b_ih, b_hh, ei, E, out);
}

// round 6
// speedup vs baseline: 1.9069x; 1.3138x over previous
#include <cuda_runtime.h>

// ============================================================================
// STGCNEncoder — fused persistent kernel, v2.
// Only row 0 of the GCN output feeds the GRU.
//  Pass A: stream dst, unsigned-min trick to find dst==0 edges (~1.6 instr/edge)
//  Pass B: u16 presence table in smem -> exact degrees of the ~34-node set
//          (~2.6 instr/edge, rare global atomics on hits)
//  Then encoder GEMVs (block/term) + gh overlap, block-0 tail (g0, gi, gates).
//  3 grid barriers total. B=1024 for 8 warps/SMSP.
// ============================================================================

#define G   148
#define B   1024
#define STR (G * B)
#define CAP 2048

__device__ unsigned long long g_bar;       // monotonic grid-barrier counter
__device__ int   g_cnt;                    // # dst==0 edges (zeroed at end of run)
__device__ int   g_srcs[CAP];
__device__ int   g_nodecnt[CAP + 2];       // per-canonical-node indeg (zeroed at end)
__device__ float g_ybuf[CAP + 1][128];
__device__ float g_gh[768];

extern __shared__ unsigned short sP[];     // presence table, N u16 entries

__device__ __forceinline__ void gbar() {
    __threadfence();
    __syncthreads();
    if (threadIdx.x == 0) {
        unsigned long long t = atomicAdd(&g_bar, 1ULL);
        unsigned long long target = t - (t % G) + G;
        volatile unsigned long long* p = &g_bar;
        while (*p < target) __nanosleep(64);
    }
    __syncthreads();
    __threadfence();
}

__global__ void __launch_bounds__(B, 1) k_fused(
    const float* __restrict__ nf, const float* __restrict__ h,
    const float* __restrict__ W_enc, const float* __restrict__ b_enc,
    const float* __restrict__ W_gcn, const float* __restrict__ b_gcn,
    const float* __restrict__ W_ih, const float* __restrict__ W_hh,
    const float* __restrict__ b_ih, const float* __restrict__ b_hh,
    const unsigned* __restrict__ w, int E, int N, float* __restrict__ out)
{
    __shared__ int   sBad;
    __shared__ float sF[64];
    const int t = threadIdx.x, lane = t & 31, wid = t >> 5;
    const int bid = blockIdx.x;
    const int gid = bid * B + t;

    // zero presence table (16B stores)
    {
        int nw = (N + 7) >> 3;
        uint4* p4 = (uint4*)sP;
        uint4 z = make_uint4(0, 0, 0, 0);
        for (int i = t; i < nw; i += B) p4[i] = z;
    }
    if (t == 0) sBad = 0;
    __syncthreads();
    // dtype detect (per block, no grid barrier): int64 ids<2^31 => odd words 0
    {
        int bad = 0;
        for (int i = t; i < 2048 && i < E; i += B) bad |= (int)w[2 * i + 1];
        if (bad) atomicOr(&sBad, 1);
    }
    __syncthreads();
    const bool is64 = (sBad == 0);

    // ---------------- Pass A: collect srcs of dst==0 edges ----------------
    if (is64) {
        const long long* srcq = (const long long*)w;
        if ((E & 1) == 0) {
            const uint4* dv = (const uint4*)(w + 2L * E);  // dst as pairs of {lo,hi}
            int nv = E >> 1;
            int i = gid;
#define CHK64(v, j) { \
    if ((v).x == 0) { int p = atomicAdd(&g_cnt, 1); if (p < CAP) g_srcs[p] = (int)srcq[2L * (j)]; } \
    if ((v).z == 0) { int p = atomicAdd(&g_cnt, 1); if (p < CAP) g_srcs[p] = (int)srcq[2L * (j) + 1]; } }
            for (; i + 3 * STR < nv; i += 4 * STR) {
                uint4 v0 = dv[i], v1 = dv[i + STR], v2 = dv[i + 2 * STR], v3 = dv[i + 3 * STR];
                unsigned m = min(min(min(v0.x, v0.z), min(v1.x, v1.z)),
                                 min(min(v2.x, v2.z), min(v3.x, v3.z)));
                if (m == 0) { CHK64(v0, i); CHK64(v1, i + STR); CHK64(v2, i + 2 * STR); CHK64(v3, i + 3 * STR); }
            }
            for (; i < nv; i += STR) {
                uint4 v = dv[i];
                if (min(v.x, v.z) == 0) { CHK64(v, i); }
            }
        } else {
            const long long* dst = srcq + E;
            for (long i = gid; i < E; i += STR)
                if (dst[i] == 0) { int p = atomicAdd(&g_cnt, 1); if (p < CAP) g_srcs[p] = (int)srcq[i]; }
        }
    } else {
        const int* srci = (const int*)w;
        if ((E & 3) == 0) {
            const uint4* dv = (const uint4*)(w + E);
            int nv = E >> 2;
            int i = gid;
#define CHK32(v, j) { \
    if ((v).x == 0) { int p = atomicAdd(&g_cnt, 1); if (p < CAP) g_srcs[p] = srci[4L * (j)]; } \
    if ((v).y == 0) { int p = atomicAdd(&g_cnt, 1); if (p < CAP) g_srcs[p] = srci[4L * (j) + 1]; } \
    if ((v).z == 0) { int p = atomicAdd(&g_cnt, 1); if (p < CAP) g_srcs[p] = srci[4L * (j) + 2]; } \
    if ((v).w == 0) { int p = atomicAdd(&g_cnt, 1); if (p < CAP) g_srcs[p] = srci[4L * (j) + 3]; } }
            for (; i + 3 * STR < nv; i += 4 * STR) {
                uint4 v0 = dv[i], v1 = dv[i + STR], v2 = dv[i + 2 * STR], v3 = dv[i + 3 * STR];
                unsigned m = min(min(min(min(v0.x, v0.y), min(v0.z, v0.w)),
                                     min(min(v1.x, v1.y), min(v1.z, v1.w))),
                                 min(min(min(v2.x, v2.y), min(v2.z, v2.w)),
                                     min(min(v3.x, v3.y), min(v3.z, v3.w))));
                if (m == 0) { CHK32(v0, i); CHK32(v1, i + STR); CHK32(v2, i + 2 * STR); CHK32(v3, i + 3 * STR); }
            }
            for (; i < nv; i += STR) {
                uint4 v = dv[i];
                if (min(min(v.x, v.y), min(v.z, v.w)) == 0) { CHK32(v, i); }
            }
        } else {
            const int* dst = srci + E;
            for (long i = gid; i < E; i += STR)
                if (dst[i] == 0) { int p = atomicAdd(&g_cnt, 1); if (p < CAP) g_srcs[p] = srci[i]; }
        }
    }
    gbar();  // -------- barrier 1 --------

    int cnt = g_cnt; if (cnt > CAP) cnt = CAP;
    const int M = cnt + 1;                      // + node-0 self-loop term

    // build presence table (every block, deterministic last-write-wins order)
    if (t == 0) {
        for (int i = 0; i < cnt; i++) sP[g_srcs[i]] = (unsigned short)(i + 1);
        if (sP[0] == 0) sP[0] = (unsigned short)(cnt + 1);
    }
    __syncthreads();

    // ---------------- Pass B: count set-membership over dst ----------------
#define CNT2(v) { unsigned p; p = sP[(v).x]; if (p) atomicAdd(&g_nodecnt[p - 1], 1); \
                              p = sP[(v).z]; if (p) atomicAdd(&g_nodecnt[p - 1], 1); }
#define CNT4(v) { unsigned p; p = sP[(v).x]; if (p) atomicAdd(&g_nodecnt[p - 1], 1); \
                              p = sP[(v).y]; if (p) atomicAdd(&g_nodecnt[p - 1], 1); \
                              p = sP[(v).z]; if (p) atomicAdd(&g_nodecnt[p - 1], 1); \
                              p = sP[(v).w]; if (p) atomicAdd(&g_nodecnt[p - 1], 1); }
    if (is64) {
        if ((E & 1) == 0) {
            const uint4* dv = (const uint4*)(w + 2L * E);
            int nv = E >> 1;
            int i = gid;
            for (; i + 3 * STR < nv; i += 4 * STR) {
                uint4 v0 = dv[i], v1 = dv[i + STR], v2 = dv[i + 2 * STR], v3 = dv[i + 3 * STR];
                unsigned a0 = sP[v0.x] | sP[v0.z];
                unsigned a1 = sP[v1.x] | sP[v1.z];
                unsigned a2 = sP[v2.x] | sP[v2.z];
                unsigned a3 = sP[v3.x] | sP[v3.z];
                if ((a0 | a1) | (a2 | a3)) { CNT2(v0); CNT2(v1); CNT2(v2); CNT2(v3); }
            }
            for (; i < nv; i += STR) {
                uint4 v = dv[i];
                if (sP[v.x] | sP[v.z]) { CNT2(v); }
            }
        } else {
            const long long* dst = ((const long long*)w) + E;
            for (long i = gid; i < E; i += STR) {
                unsigned p = sP[(unsigned)dst[i]];
                if (p) atomicAdd(&g_nodecnt[p - 1], 1);
            }
        }
    } else {
        if ((E & 3) == 0) {
            const uint4* dv = (const uint4*)(w + E);
            int nv = E >> 2;
            int i = gid;
            for (; i + 3 * STR < nv; i += 4 * STR) {
                uint4 v0 = dv[i], v1 = dv[i + STR], v2 = dv[i + 2 * STR], v3 = dv[i + 3 * STR];
                unsigned a0 = (sP[v0.x] | sP[v0.y]) | (sP[v0.z] | sP[v0.w]);
                unsigned a1 = (sP[v1.x] | sP[v1.y]) | (sP[v1.z] | sP[v1.w]);
                unsigned a2 = (sP[v2.x] | sP[v2.y]) | (sP[v2.z] | sP[v2.w]);
                unsigned a3 = (sP[v3.x] | sP[v3.y]) | (sP[v3.z] | sP[v3.w]);
                if ((a0 | a1) | (a2 | a3)) { CNT4(v0); CNT4(v1); CNT4(v2); CNT4(v3); }
            }
            for (; i < nv; i += STR) {
                uint4 v = dv[i];
                if ((sP[v.x] | sP[v.y]) | (sP[v.z] | sP[v.w])) { CNT4(v); }
            }
        } else {
            const int* dst = ((const int*)w) + E;
            for (long i = gid; i < E; i += STR) {
                unsigned p = sP[(unsigned)dst[i]];
                if (p) atomicAdd(&g_nodecnt[p - 1], 1);
            }
        }
    }
    gbar();  // -------- barrier 2 --------

    // ---------------- Encoder terms (block per term) + gh overlap ----------
    for (int i = bid; i < M; i += G) {
        int s = (i < cnt) ? g_srcs[i] : 0;
        float dg  = (float)g_nodecnt[sP[s] - 1] + 1.0f;   // +1 self loop
        float dg0 = (float)g_nodecnt[sP[0] - 1] + 1.0f;
        float wt = rsqrtf(dg) * rsqrtf(dg0);
        if (t < 64) sF[t] = nf[(long)s * 64 + t];
        __syncthreads();
        float f0 = sF[lane], f1 = sF[lane + 32];
        #pragma unroll
        for (int jj = 0; jj < 4; jj++) {
            int j = wid * 4 + jj;
            const float* wr = W_enc + j * 64;
            float a = wr[lane] * f0 + wr[lane + 32] * f1;
            #pragma unroll
            for (int o = 16; o; o >>= 1) a += __shfl_down_sync(0xffffffffu, a, o);
            if (lane == 0) g_ybuf[i][j] = wt * fmaxf(a + b_enc[j], 0.0f);
        }
        __syncthreads();
    }
    if (bid >= 96) {                      // gh = W_hh @ h + b_hh (indep of g0)
        int r = (bid - 96) * 32 + wid;
        if (r < 768) {
            const float* wr = W_hh + r * 256;
            float a = 0.0f;
            #pragma unroll
            for (int kk = 0; kk < 8; kk++) a += wr[kk * 32 + lane] * h[kk * 32 + lane];
            #pragma unroll
            for (int o = 16; o; o >>= 1) a += __shfl_down_sync(0xffffffffu, a, o);
            if (lane == 0) g_gh[r] = a + b_hh[r];
        }
    }
    gbar();  // -------- barrier 3 --------

    // ---------------- Block-0 tail: xsum, g0, gi, gates, reset -------------
    if (bid == 0) {
        float* sX  = (float*)sP;          // presence no longer needed: reuse smem
        float* sG0 = sX + 128;
        float* sGi = sG0 + 128;
        if (t < 128) {
            float xs = 0.0f;
            for (int i = 0; i < M; i++) xs += g_ybuf[i][t];
            sX[t] = xs;
        }
        __syncthreads();
        #pragma unroll
        for (int jj = 0; jj < 4; jj++) {
            int j = wid * 4 + jj;
            float a = 0.0f;
            #pragma unroll
            for (int kk = 0; kk < 4; kk++)
                a += W_gcn[j * 128 + kk * 32 + lane] * sX[kk * 32 + lane];
            #pragma unroll
            for (int o = 16; o; o >>= 1) a += __shfl_down_sync(0xffffffffu, a, o);
            if (lane == 0) sG0[j] = fmaxf(a + b_gcn[j], 0.0f);
        }
        __syncthreads();
        #pragma unroll
        for (int q = 0; q < 24; q++) {
            int r = q * 32 + wid;
            const float* wr = W_ih + r * 128;
            float a = 0.0f;
            #pragma unroll
            for (int kk = 0; kk < 4; kk++)
                a += wr[kk * 32 + lane] * sG0[kk * 32 + lane];
            #pragma unroll
            for (int o = 16; o; o >>= 1) a += __shfl_down_sync(0xffffffffu, a, o);
            if (lane == 0) sGi[r] = a + b_ih[r];
        }
        __syncthreads();
        if (t < 256) {
            float r_ = 1.0f / (1.0f + expf(-(sGi[t] + g_gh[t])));
            float z  = 1.0f / (1.0f + expf(-(sGi[256 + t] + g_gh[256 + t])));
            float nn = tanhf(sGi[512 + t] + r_ * g_gh[512 + t]);
            out[t] = (1.0f - z) * nn + z * h[t];
        }
        // reset device globals for the next (replayed) run
        for (int i = t; i < cnt + 2; i += B) g_nodecnt[i] = 0;
        if (t == 0) g_cnt = 0;
    }
}

// ---------------------------------------------------------------------------
extern "C" void kernel_launch(void* const* d_in, const int* in_sizes, int n_in,
                              void* d_out, int out_size) {
    const float* nf    = (const float*)d_in[0];
    // d_in[1] = edge_attr (unused by reference)
    const float* h     = (const float*)d_in[2];
    const float* W_enc = (const float*)d_in[3];
    const float* b_enc = (const float*)d_in[4];
    const float* W_gcn = (const float*)d_in[5];
    const float* b_gcn = (const float*)d_in[6];
    const float* W_ih  = (const float*)d_in[7];
    const float* W_hh  = (const float*)d_in[8];
    const float* b_ih  = (const float*)d_in[9];
    const float* b_hh  = (const float*)d_in[10];
    const unsigned* ei = (const unsigned*)d_in[11];
    int E = in_sizes[11] / 2;
    int N = in_sizes[0] / 64;
    float* out = (float*)d_out;

    int smem = (2 * N + 15) & ~15;
    if (smem < 8192) smem = 8192;                  // room for tail reuse arrays
    cudaFuncSetAttribute(k_fused, cudaFuncAttributeMaxDynamicSharedMemorySize, smem);

    k_fused<<<G, B, smem>>>(nf, h, W_enc, b_enc, W_gcn, b_gcn,
                            W_ih, W_hh, b_ih, b_hh, ei, E, N, out);
}